// round 1
// baseline (speedup 1.0000x reference)
#include <cuda_runtime.h>

// Problem constants (fixed shapes for RNNCell_62122406969624)
#define TT 512
#define BB 16384
#define HH 32

typedef unsigned long long u64;

// ---- packed f32x2 helpers (sm_100+ PTX; ptxas never auto-fuses these) ----
__device__ __forceinline__ u64 fma2(u64 a, u64 b, u64 c) {
    u64 d; asm("fma.rn.f32x2 %0,%1,%2,%3;" : "=l"(d) : "l"(a), "l"(b), "l"(c)); return d;
}
__device__ __forceinline__ u64 mul2(u64 a, u64 b) {
    u64 d; asm("mul.rn.f32x2 %0,%1,%2;" : "=l"(d) : "l"(a), "l"(b)); return d;
}
__device__ __forceinline__ u64 pack2(float lo, float hi) {
    u64 r; asm("mov.b64 %0,{%1,%2};" : "=l"(r) : "f"(lo), "f"(hi)); return r;
}
__device__ __forceinline__ u64 dup2(float x) { return pack2(x, x); }
__device__ __forceinline__ void unpack2(u64 v, float& lo, float& hi) {
    asm("mov.b64 {%0,%1},%2;" : "=f"(lo), "=f"(hi) : "l"(v));
}

// Numerically-stable softplus + sigmoid sharing one exp:
//   u = exp(-|z|);  softplus = max(z,0) + log(1+u);  sigmoid = z>=0 ? 1/(1+u) : 1 - 1/(1+u)
__device__ __forceinline__ void sp_sig(float z, float& sp, float& sg) {
    float u = __expf(-fabsf(z));
    float d = 1.0f + u;
    float r = __fdividef(1.0f, d);
    sp = fmaxf(z, 0.0f) + __logf(d);
    sg = (z >= 0.0f) ? r : 1.0f - r;
}
__device__ __forceinline__ float sigf(float z) {
    float u = __expf(-fabsf(z));
    float r = __fdividef(1.0f, 1.0f + u);
    return (z >= 0.0f) ? r : 1.0f - r;
}

__global__ void __launch_bounds__(64) rnncell_scan_kernel(
    const float* __restrict__ eps, const float* __restrict__ hs,
    const float* __restrict__ W1,  const float* __restrict__ b1,
    const float* __restrict__ W2,  const float* __restrict__ b2,
    const float* __restrict__ W3,  float* __restrict__ out)
{
    __shared__ __align__(16) float sW2 [HH * HH];   // W2[k][j], row-major
    __shared__ __align__(16) float sW2T[HH * HH];   // W2T[j][k] = W2[k][j]
    __shared__ __align__(16) float sw1a[HH];
    __shared__ __align__(16) float sw1b[HH];
    __shared__ __align__(16) float sb1 [HH];
    __shared__ __align__(16) float sb2 [HH];
    __shared__ __align__(16) float sw3 [HH];

    const int tid = threadIdx.x;
    for (int i = tid; i < HH * HH; i += blockDim.x) {
        float w = W2[i];
        sW2[i] = w;
        sW2T[(i & 31) * HH + (i >> 5)] = w;
    }
    if (tid < HH) {
        sw1a[tid] = W1[tid];        // W1[0, j]
        sw1b[tid] = W1[HH + tid];   // W1[1, j]
        sb1 [tid] = b1[tid];
        sb2 [tid] = b2[tid];
        sw3 [tid] = W3[tid];        // W3[j, 0]
    }
    __syncthreads();

    const u64* __restrict__ w2p  = (const u64*)sW2;
    const u64* __restrict__ w2tp = (const u64*)sW2T;
    const u64* __restrict__ w1ap = (const u64*)sw1a;
    const u64* __restrict__ w1bp = (const u64*)sw1b;
    const u64* __restrict__ b1p  = (const u64*)sb1;
    const u64* __restrict__ b2p  = (const u64*)sb2;

    const int gid = blockIdx.x * 64 + tid;   // 0..16383

    float gamma = 0.0f;
    float ec = eps[gid];
    float hc = hs[gid];

    for (int t = 0; t < TT; ++t) {
        // prefetch next step's inputs (hidden under ~2800-cycle step body)
        const int tn = (t + 1 < TT) ? t + 1 : t;
        float en = eps[(size_t)tn * BB + gid];
        float hn = hs [(size_t)tn * BB + gid];

        // ---- layer 1: z1 = eps*w1a + gamma*w1b + b1 ; a1 = softplus ; sig1 ----
        u64 e2 = dup2(ec);
        u64 g2 = dup2(gamma);
        float a1s[HH];       // softplus(z1), scalar (broadcast operands for matvec1)
        u64   s1p[HH / 2];   // sigmoid(z1), packed
        #pragma unroll
        for (int j = 0; j < 16; ++j) {
            u64 z = fma2(e2, w1ap[j], fma2(g2, w1bp[j], b1p[j]));
            float za, zb; unpack2(z, za, zb);
            float spa, sga, spb, sgb;
            sp_sig(za, spa, sga);
            sp_sig(zb, spb, sgb);
            a1s[2 * j]     = spa;
            a1s[2 * j + 1] = spb;
            s1p[j] = pack2(sga, sgb);
        }

        // ---- matvec1: z2[j] = b2[j] + sum_k a1[k] * W2[k][j] (packed over j) ----
        u64 acc[16];
        #pragma unroll
        for (int j = 0; j < 16; ++j) acc[j] = b2p[j];
        #pragma unroll
        for (int k = 0; k < HH; ++k) {
            u64 ak = dup2(a1s[k]);
            const ulonglong2* row = (const ulonglong2*)(w2p + k * 16);
            #pragma unroll
            for (int j = 0; j < 8; ++j) {
                ulonglong2 w = row[j];   // LDS.128 broadcast
                acc[2 * j]     = fma2(ak, w.x, acc[2 * j]);
                acc[2 * j + 1] = fma2(ak, w.y, acc[2 * j + 1]);
            }
        }

        // ---- v2 = sigmoid(z2) * W3 (scalar broadcast operands for matvec2) ----
        float v2s[HH];
        #pragma unroll
        for (int j = 0; j < 16; ++j) {
            float za, zb; unpack2(acc[j], za, zb);
            v2s[2 * j]     = sigf(za) * sw3[2 * j];
            v2s[2 * j + 1] = sigf(zb) * sw3[2 * j + 1];
        }

        // ---- matvec2: t[k] = sum_j v2[j] * W2[k][j] = sum_j v2[j] * W2T[j][k] ----
        u64 tacc[16];
        #pragma unroll
        for (int j = 0; j < 16; ++j) tacc[j] = 0ull;
        #pragma unroll
        for (int k = 0; k < HH; ++k) {
            u64 vk = dup2(v2s[k]);
            const ulonglong2* row = (const ulonglong2*)(w2tp + k * 16);
            #pragma unroll
            for (int j = 0; j < 8; ++j) {
                ulonglong2 w = row[j];
                tacc[2 * j]     = fma2(vk, w.x, tacc[2 * j]);
                tacc[2 * j + 1] = fma2(vk, w.y, tacc[2 * j + 1]);
            }
        }

        // ---- v1 = sig1 .* t ; g0 = <v1, w1a> ; g1 = <v1, w1b> ----
        u64 g0p = 0ull, g1p = 0ull;
        #pragma unroll
        for (int j = 0; j < 16; ++j) {
            u64 v1 = mul2(s1p[j], tacc[j]);
            g0p = fma2(v1, w1ap[j], g0p);
            g1p = fma2(v1, w1bp[j], g1p);
        }
        float g0a, g0b, g1a, g1b;
        unpack2(g0p, g0a, g0b);
        unpack2(g1p, g1a, g1b);
        float g0 = g0a + g0b;
        float g1 = g1a + g1b;

        out[(size_t)t * BB + gid] = g0;
        gamma = fmaf(hc, -g1, gamma);   // gamma += hs * (-g1)

        ec = en;
        hc = hn;
    }
}

extern "C" void kernel_launch(void* const* d_in, const int* in_sizes, int n_in,
                              void* d_out, int out_size) {
    const float* eps = (const float*)d_in[0];
    const float* hs  = (const float*)d_in[1];
    const float* W1  = (const float*)d_in[2];
    const float* b1  = (const float*)d_in[3];
    const float* W2  = (const float*)d_in[4];
    const float* b2  = (const float*)d_in[5];
    const float* W3  = (const float*)d_in[6];
    float* out = (float*)d_out;

    // 16384 lanes, 64 thr/CTA -> 256 CTAs (>=148 avoids low-grid issue throttle)
    rnncell_scan_kernel<<<BB / 64, 64>>>(eps, hs, W1, b1, W2, b2, W3, out);
}

// round 2
// speedup vs baseline: 9.8606x; 9.8606x over previous
#include <cuda_runtime.h>

#define TT 512
#define BB 16384
#define HH 32
#define TPL 4          // threads per batch lane
#define UPT 8          // hidden units per thread
#define BLK 128

typedef unsigned long long u64;

// ---- packed f32x2 helpers (ptxas never auto-fuses; PTX-only on sm_10x) ----
__device__ __forceinline__ u64 fma2(u64 a, u64 b, u64 c) {
    u64 d; asm("fma.rn.f32x2 %0,%1,%2,%3;" : "=l"(d) : "l"(a), "l"(b), "l"(c)); return d;
}
__device__ __forceinline__ u64 mul2(u64 a, u64 b) {
    u64 d; asm("mul.rn.f32x2 %0,%1,%2;" : "=l"(d) : "l"(a), "l"(b)); return d;
}
__device__ __forceinline__ u64 pack2(float lo, float hi) {
    u64 r; asm("mov.b64 %0,{%1,%2};" : "=l"(r) : "f"(lo), "f"(hi)); return r;
}
__device__ __forceinline__ u64 dup2(float x) { return pack2(x, x); }
__device__ __forceinline__ void unpack2(u64 v, float& lo, float& hi) {
    asm("mov.b64 {%0,%1},%2;" : "=f"(lo), "=f"(hi) : "l"(v));
}

// stable softplus + sigmoid sharing one exp
__device__ __forceinline__ void sp_sig(float z, float& sp, float& sg) {
    float u = __expf(-fabsf(z));
    float d = 1.0f + u;
    float r = __fdividef(1.0f, d);
    sp = fmaxf(z, 0.0f) + __logf(d);
    sg = (z >= 0.0f) ? r : 1.0f - r;
}
__device__ __forceinline__ float sigf(float z) {
    float u = __expf(-fabsf(z));
    float r = __fdividef(1.0f, 1.0f + u);
    return (z >= 0.0f) ? r : 1.0f - r;
}

__global__ void __launch_bounds__(BLK, 4) rnncell_scan4_kernel(
    const float* __restrict__ eps, const float* __restrict__ hs,
    const float* __restrict__ W1,  const float* __restrict__ b1,
    const float* __restrict__ W2,  const float* __restrict__ b2,
    const float* __restrict__ W3,  float* __restrict__ out)
{
    __shared__ __align__(16) float sW2 [HH * HH];   // W2[k][j]
    __shared__ __align__(16) float sW2T[HH * HH];   // W2T[j][k] = W2[k][j]

    const int tid = threadIdx.x;
    for (int i = tid; i < HH * HH; i += BLK) {
        float w = W2[i];
        sW2[i] = w;
        sW2T[(i & 31) * HH + (i >> 5)] = w;
    }
    __syncthreads();

    const int gt      = blockIdx.x * BLK + tid;   // global thread
    const int gid     = gt >> 2;                  // batch lane 0..16383
    const int quarter = gt & 3;                   // which 8-unit chunk I own
    const int co      = quarter * UPT;            // my unit offset (0,8,16,24)
    const int lane    = tid & 31;
    const int lbase   = lane & ~3;                // first lane of my 4-group

    // loop-invariant per-chunk weights in registers (packed where useful)
    u64 w1ap[4], w1bp[4], b1p[4], b2p[4];
    float w3s[UPT];
    #pragma unroll
    for (int j = 0; j < 4; ++j) {
        w1ap[j] = pack2(W1[co + 2*j],      W1[co + 2*j + 1]);
        w1bp[j] = pack2(W1[HH + co + 2*j], W1[HH + co + 2*j + 1]);
        b1p [j] = pack2(b1[co + 2*j],      b1[co + 2*j + 1]);
        b2p [j] = pack2(b2[co + 2*j],      b2[co + 2*j + 1]);
    }
    #pragma unroll
    for (int j = 0; j < UPT; ++j) w3s[j] = W3[co + j];

    float gamma = 0.0f;
    float ec = eps[gid];
    float hc = hs[gid];

    for (int t = 0; t < TT; ++t) {
        // prefetch next step inputs (hidden under the step body)
        const int tn = (t + 1 < TT) ? t + 1 : t;
        float en = eps[(size_t)tn * BB + gid];
        float hn = hs [(size_t)tn * BB + gid];

        // ---- layer 1 (my 8 units): z1 = e*w1a + gamma*w1b + b1 ----
        const u64 e2 = dup2(ec);
        const u64 g2 = dup2(gamma);
        float a1s[UPT];   // softplus(z1) - scalar, gets shfl-broadcast
        u64   s1p[4];     // sigmoid(z1) - packed, used at the end
        #pragma unroll
        for (int j = 0; j < 4; ++j) {
            u64 z = fma2(e2, w1ap[j], fma2(g2, w1bp[j], b1p[j]));
            float za, zb; unpack2(z, za, zb);
            float spa, sga, spb, sgb;
            sp_sig(za, spa, sga);
            sp_sig(zb, spb, sgb);
            a1s[2*j]   = spa;
            a1s[2*j+1] = spb;
            s1p[j] = pack2(sga, sgb);
        }

        // ---- matvec1: z2[j] (my 8 cols) = b2 + sum_k a1[k] * W2[k][j] ----
        u64 acc[4];
        #pragma unroll
        for (int j = 0; j < 4; ++j) acc[j] = b2p[j];
        #pragma unroll
        for (int q = 0; q < TPL; ++q) {
            #pragma unroll
            for (int kk = 0; kk < UPT; ++kk) {
                float aks = __shfl_sync(0xffffffffu, a1s[kk], lbase + q);
                u64 ak = dup2(aks);
                const ulonglong2* row =
                    (const ulonglong2*)(sW2 + (q * UPT + kk) * HH + co);
                ulonglong2 w0 = row[0];
                ulonglong2 w1 = row[1];
                acc[0] = fma2(ak, w0.x, acc[0]);
                acc[1] = fma2(ak, w0.y, acc[1]);
                acc[2] = fma2(ak, w1.x, acc[2]);
                acc[3] = fma2(ak, w1.y, acc[3]);
            }
        }

        // ---- v2 = sigmoid(z2) * W3 (my 8, scalar for broadcast) ----
        float v2s[UPT];
        #pragma unroll
        for (int j = 0; j < 4; ++j) {
            float za, zb; unpack2(acc[j], za, zb);
            v2s[2*j]   = sigf(za) * w3s[2*j];
            v2s[2*j+1] = sigf(zb) * w3s[2*j+1];
        }

        // ---- matvec2: t[k] (my 8 rows) = sum_j v2[j] * W2T[j][k] ----
        u64 tacc[4];
        #pragma unroll
        for (int j = 0; j < 4; ++j) tacc[j] = 0ull;
        #pragma unroll
        for (int q = 0; q < TPL; ++q) {
            #pragma unroll
            for (int jj = 0; jj < UPT; ++jj) {
                float vjs = __shfl_sync(0xffffffffu, v2s[jj], lbase + q);
                u64 vj = dup2(vjs);
                const ulonglong2* row =
                    (const ulonglong2*)(sW2T + (q * UPT + jj) * HH + co);
                ulonglong2 w0 = row[0];
                ulonglong2 w1 = row[1];
                tacc[0] = fma2(vj, w0.x, tacc[0]);
                tacc[1] = fma2(vj, w0.y, tacc[1]);
                tacc[2] = fma2(vj, w1.x, tacc[2]);
                tacc[3] = fma2(vj, w1.y, tacc[3]);
            }
        }

        // ---- v1 = sig1 .* t ; partial dots with w1a / w1b ----
        u64 g0p = 0ull, g1p = 0ull;
        #pragma unroll
        for (int j = 0; j < 4; ++j) {
            u64 v1 = mul2(s1p[j], tacc[j]);
            g0p = fma2(v1, w1ap[j], g0p);
            g1p = fma2(v1, w1bp[j], g1p);
        }
        float g0a, g0b, g1a, g1b;
        unpack2(g0p, g0a, g0b);
        unpack2(g1p, g1a, g1b);
        float g0 = g0a + g0b;
        float g1 = g1a + g1b;

        // butterfly over the 4-lane group: all lanes end with identical sums
        g0 += __shfl_xor_sync(0xffffffffu, g0, 1);
        g0 += __shfl_xor_sync(0xffffffffu, g0, 2);
        g1 += __shfl_xor_sync(0xffffffffu, g1, 1);
        g1 += __shfl_xor_sync(0xffffffffu, g1, 2);

        if (quarter == 0) out[(size_t)t * BB + gid] = g0;
        gamma = fmaf(hc, -g1, gamma);   // gamma += hs * (-g1), replicated

        ec = en;
        hc = hn;
    }
}

extern "C" void kernel_launch(void* const* d_in, const int* in_sizes, int n_in,
                              void* d_out, int out_size) {
    const float* eps = (const float*)d_in[0];
    const float* hs  = (const float*)d_in[1];
    const float* W1  = (const float*)d_in[2];
    const float* b1  = (const float*)d_in[3];
    const float* W2  = (const float*)d_in[4];
    const float* b2  = (const float*)d_in[5];
    const float* W3  = (const float*)d_in[6];
    float* out = (float*)d_out;

    // 16384 lanes x 4 threads = 65536 threads, 512 CTAs of 128
    rnncell_scan4_kernel<<<(BB * TPL) / BLK, BLK>>>(eps, hs, W1, b1, W2, b2, W3, out);
}

// round 3
// speedup vs baseline: 17.7097x; 1.7960x over previous
#include <cuda_runtime.h>

#define TT 512
#define BB 16384
#define HH 32
#define RL 2              // batch lanes per thread
#define BLK 128
#define LPC 64            // lanes per CTA = (BLK/4) * RL
#define ASTRIDE 36        // padded floats per lane row in sAct

typedef unsigned long long u64;

// ---- packed f32x2 helpers (PTX-only; ptxas never auto-fuses) ----
__device__ __forceinline__ u64 fma2(u64 a, u64 b, u64 c) {
    u64 d; asm("fma.rn.f32x2 %0,%1,%2,%3;" : "=l"(d) : "l"(a), "l"(b), "l"(c)); return d;
}
__device__ __forceinline__ u64 mul2(u64 a, u64 b) {
    u64 d; asm("mul.rn.f32x2 %0,%1,%2;" : "=l"(d) : "l"(a), "l"(b)); return d;
}
__device__ __forceinline__ u64 pack2(float lo, float hi) {
    u64 r; asm("mov.b64 %0,{%1,%2};" : "=l"(r) : "f"(lo), "f"(hi)); return r;
}
__device__ __forceinline__ u64 dup2(float x) { return pack2(x, x); }
__device__ __forceinline__ void unpack2(u64 v, float& lo, float& hi) {
    asm("mov.b64 {%0,%1},%2;" : "=f"(lo), "=f"(hi) : "l"(v));
}

// stable softplus + sigmoid sharing one exp
__device__ __forceinline__ void sp_sig(float z, float& sp, float& sg) {
    float u = __expf(-fabsf(z));
    float d = 1.0f + u;
    float r = __fdividef(1.0f, d);
    sp = fmaxf(z, 0.0f) + __logf(d);
    sg = (z >= 0.0f) ? r : 1.0f - r;
}
__device__ __forceinline__ float sigf(float z) {
    float u = __expf(-fabsf(z));
    float r = __fdividef(1.0f, 1.0f + u);
    return (z >= 0.0f) ? r : 1.0f - r;
}

__global__ void __launch_bounds__(BLK, 2) rnncell_r2_kernel(
    const float* __restrict__ eps, const float* __restrict__ hs,
    const float* __restrict__ W1,  const float* __restrict__ b1,
    const float* __restrict__ W2,  const float* __restrict__ b2,
    const float* __restrict__ W3,  float* __restrict__ out)
{
    __shared__ __align__(16) float sW2 [HH * HH];       // W2[k][j]
    __shared__ __align__(16) float sW2T[HH * HH];       // W2T[j][k]
    __shared__ __align__(16) float sAct[LPC * ASTRIDE]; // per-lane activation rows

    const int tid = threadIdx.x;
    for (int i = tid; i < HH * HH; i += BLK) {
        float w = W2[i];
        sW2[i] = w;
        sW2T[(i & 31) * HH + (i >> 5)] = w;
    }
    __syncthreads();

    const int quarter = tid & 3;          // which 8-unit chunk I own
    const int grp     = tid >> 2;         // group 0..31 within CTA
    const int co      = quarter * 8;      // unit offset

    // local lanes: r=0 -> grp, r=1 -> grp+32  (consecutive within an act-load instr)
    int lanes[RL];
    int gids [RL];
    float* act[RL];
    #pragma unroll
    for (int r = 0; r < RL; ++r) {
        lanes[r] = grp + 32 * r;
        gids [r] = blockIdx.x * LPC + lanes[r];
        act  [r] = &sAct[lanes[r] * ASTRIDE];
    }

    // loop-invariant per-chunk weights in registers
    u64 w1ap[4], w1bp[4], b1p[4], b2p[4];
    float w3s[8];
    #pragma unroll
    for (int j = 0; j < 4; ++j) {
        w1ap[j] = pack2(W1[co + 2*j],      W1[co + 2*j + 1]);
        w1bp[j] = pack2(W1[HH + co + 2*j], W1[HH + co + 2*j + 1]);
        b1p [j] = pack2(b1[co + 2*j],      b1[co + 2*j + 1]);
        b2p [j] = pack2(b2[co + 2*j],      b2[co + 2*j + 1]);
    }
    #pragma unroll
    for (int j = 0; j < 8; ++j) w3s[j] = W3[co + j];

    float gam[RL], ec[RL], hc[RL];
    #pragma unroll
    for (int r = 0; r < RL; ++r) {
        gam[r] = 0.0f;
        ec[r] = eps[gids[r]];
        hc[r] = hs [gids[r]];
    }

    for (int t = 0; t < TT; ++t) {
        // prefetch next step inputs
        const int tn = (t + 1 < TT) ? t + 1 : t;
        float en[RL], hn[RL];
        #pragma unroll
        for (int r = 0; r < RL; ++r) {
            en[r] = eps[(size_t)tn * BB + gids[r]];
            hn[r] = hs [(size_t)tn * BB + gids[r]];
        }

        // ---- layer 1 (my 8 units x RL lanes): z1 -> softplus (staged), sigmoid (regs)
        u64 s1p[RL][4];
        #pragma unroll
        for (int r = 0; r < RL; ++r) {
            const u64 e2 = dup2(ec[r]);
            const u64 g2 = dup2(gam[r]);
            float a1v[8];
            #pragma unroll
            for (int j = 0; j < 4; ++j) {
                u64 z = fma2(e2, w1ap[j], fma2(g2, w1bp[j], b1p[j]));
                float za, zb; unpack2(z, za, zb);
                float spa, sga, spb, sgb;
                sp_sig(za, spa, sga);
                sp_sig(zb, spb, sgb);
                a1v[2*j]   = spa;
                a1v[2*j+1] = spb;
                s1p[r][j]  = pack2(sga, sgb);
            }
            // stage softplus values for this lane
            *(float4*)(act[r] + co)     = make_float4(a1v[0], a1v[1], a1v[2], a1v[3]);
            *(float4*)(act[r] + co + 4) = make_float4(a1v[4], a1v[5], a1v[6], a1v[7]);
        }
        __syncwarp();

        // ---- matvec1: z2[my 8 cols] = b2 + sum_k a1[k] * W2[k][.] ----
        u64 acc[RL][4];
        #pragma unroll
        for (int r = 0; r < RL; ++r)
            #pragma unroll
            for (int j = 0; j < 4; ++j) acc[r][j] = b2p[j];

        #pragma unroll
        for (int q = 0; q < 4; ++q) {
            float av[RL][8];
            #pragma unroll
            for (int r = 0; r < RL; ++r) {
                float4 t0 = *(const float4*)(act[r] + q * 8);
                float4 t1 = *(const float4*)(act[r] + q * 8 + 4);
                av[r][0]=t0.x; av[r][1]=t0.y; av[r][2]=t0.z; av[r][3]=t0.w;
                av[r][4]=t1.x; av[r][5]=t1.y; av[r][6]=t1.z; av[r][7]=t1.w;
            }
            #pragma unroll
            for (int kk = 0; kk < 8; ++kk) {
                const float* wr = sW2 + (q * 8 + kk) * HH + co;
                ulonglong2 wlo = *(const ulonglong2*)wr;
                ulonglong2 whi = *(const ulonglong2*)(wr + 4);
                #pragma unroll
                for (int r = 0; r < RL; ++r) {
                    u64 ak = dup2(av[r][kk]);
                    acc[r][0] = fma2(ak, wlo.x, acc[r][0]);
                    acc[r][1] = fma2(ak, wlo.y, acc[r][1]);
                    acc[r][2] = fma2(ak, whi.x, acc[r][2]);
                    acc[r][3] = fma2(ak, whi.y, acc[r][3]);
                }
            }
        }
        __syncwarp();   // all group threads done reading a1 before overwrite

        // ---- v2 = sigmoid(z2) * W3, staged to smem ----
        #pragma unroll
        for (int r = 0; r < RL; ++r) {
            float v2v[8];
            #pragma unroll
            for (int j = 0; j < 4; ++j) {
                float za, zb; unpack2(acc[r][j], za, zb);
                v2v[2*j]   = sigf(za) * w3s[2*j];
                v2v[2*j+1] = sigf(zb) * w3s[2*j+1];
            }
            *(float4*)(act[r] + co)     = make_float4(v2v[0], v2v[1], v2v[2], v2v[3]);
            *(float4*)(act[r] + co + 4) = make_float4(v2v[4], v2v[5], v2v[6], v2v[7]);
        }
        __syncwarp();

        // ---- matvec2: t[my 8 rows] = sum_j v2[j] * W2T[j][.] ----
        u64 tacc[RL][4];
        #pragma unroll
        for (int r = 0; r < RL; ++r)
            #pragma unroll
            for (int j = 0; j < 4; ++j) tacc[r][j] = 0ull;

        #pragma unroll
        for (int q = 0; q < 4; ++q) {
            float vv[RL][8];
            #pragma unroll
            for (int r = 0; r < RL; ++r) {
                float4 t0 = *(const float4*)(act[r] + q * 8);
                float4 t1 = *(const float4*)(act[r] + q * 8 + 4);
                vv[r][0]=t0.x; vv[r][1]=t0.y; vv[r][2]=t0.z; vv[r][3]=t0.w;
                vv[r][4]=t1.x; vv[r][5]=t1.y; vv[r][6]=t1.z; vv[r][7]=t1.w;
            }
            #pragma unroll
            for (int kk = 0; kk < 8; ++kk) {
                const float* wr = sW2T + (q * 8 + kk) * HH + co;
                ulonglong2 wlo = *(const ulonglong2*)wr;
                ulonglong2 whi = *(const ulonglong2*)(wr + 4);
                #pragma unroll
                for (int r = 0; r < RL; ++r) {
                    u64 vk = dup2(vv[r][kk]);
                    tacc[r][0] = fma2(vk, wlo.x, tacc[r][0]);
                    tacc[r][1] = fma2(vk, wlo.y, tacc[r][1]);
                    tacc[r][2] = fma2(vk, whi.x, tacc[r][2]);
                    tacc[r][3] = fma2(vk, whi.y, tacc[r][3]);
                }
            }
        }

        // ---- v1 = sig1 .* t ; dots with w1a / w1b ; 4-thread butterfly ----
        #pragma unroll
        for (int r = 0; r < RL; ++r) {
            u64 g0p = 0ull, g1p = 0ull;
            #pragma unroll
            for (int j = 0; j < 4; ++j) {
                u64 v1 = mul2(s1p[r][j], tacc[r][j]);
                g0p = fma2(v1, w1ap[j], g0p);
                g1p = fma2(v1, w1bp[j], g1p);
            }
            float g0a, g0b, g1a, g1b;
            unpack2(g0p, g0a, g0b);
            unpack2(g1p, g1a, g1b);
            float g0 = g0a + g0b;
            float g1 = g1a + g1b;

            g0 += __shfl_xor_sync(0xffffffffu, g0, 1);
            g0 += __shfl_xor_sync(0xffffffffu, g0, 2);
            g1 += __shfl_xor_sync(0xffffffffu, g1, 1);
            g1 += __shfl_xor_sync(0xffffffffu, g1, 2);

            if (quarter == 0) out[(size_t)t * BB + gids[r]] = g0;
            gam[r] = fmaf(hc[r], -g1, gam[r]);   // gamma += hs * (-g1), replicated

            ec[r] = en[r];
            hc[r] = hn[r];
        }
    }
}

extern "C" void kernel_launch(void* const* d_in, const int* in_sizes, int n_in,
                              void* d_out, int out_size) {
    const float* eps = (const float*)d_in[0];
    const float* hs  = (const float*)d_in[1];
    const float* W1  = (const float*)d_in[2];
    const float* b1  = (const float*)d_in[3];
    const float* W2  = (const float*)d_in[4];
    const float* b2  = (const float*)d_in[5];
    const float* W3  = (const float*)d_in[6];
    float* out = (float*)d_out;

    // 16384 lanes / 64 lanes-per-CTA = 256 CTAs of 128 threads
    rnncell_r2_kernel<<<BB / LPC, BLK>>>(eps, hs, W1, b1, W2, b2, W3, out);
}